// round 8
// baseline (speedup 1.0000x reference)
#include <cuda_runtime.h>

#define NN 30000
#define EE 480000
#define CC 32
#define LL 2
#define PP 7
#define HH 4
#define NTT 15
#define EPSF 1e-8f
#define EPW 8

static_assert(EE % EPW == 0, "edge tiles are exact");

// ---------------- static device scratch (no allocation allowed) ----------------
__device__ float  g_f0[2][NN * CC];
__device__ float4 g_f1[2][NN * CC];        // {x,y,z,pad}
__device__ float4 g_f2[2][NN * CC];        // components 0..3
__device__ float  g_f2b[2][NN * CC];       // component 4
__device__ float  g_q[NN * CC];
// per-edge data stored in CSR (dst-sorted) order:
__device__ float  g_m0[EE * CC];           // layer-0 streams (scalar, no padding waste)
__device__ float  g_u3[EE * CC];
__device__ float  g_u5[EE * CC];
__device__ float4 g_pk[EE * CC];           // layer-1 packed {m0,u3,u5,u4}
__device__ float  g_u6[EE * CC];
__device__ float  g_logit[EE * HH];
__device__ int g_srcp[EE];      // src node id, CSR order
__device__ int g_pos[EE];       // edge -> CSR slot
__device__ int g_cnt[NN + 1];
__device__ int g_off[NN + 1];
__device__ int g_cur[NN];

// ---------------- init: f0 <- node_l0, cnt <- 0, then count dst degrees ----------
// (count folded in: the NN*CC grid covers the EE range as well)
__global__ void k_init(const float* __restrict__ node_l0, const int* __restrict__ edst) {
    int i = blockIdx.x * blockDim.x + threadIdx.x;
    if (i < NN * CC) g_f0[0][i] = node_l0[i];
    if (i <= NN) g_cnt[i] = 0;
    // ensure all zeroing in this block's index range is globally visible before
    // counting begins: different blocks may race zero vs atomic on the same word.
    // Avoided by splitting: counts happen in a second kernel below.
}

__global__ void k_count(const int* __restrict__ edst) {
    int e = blockIdx.x * blockDim.x + threadIdx.x;
    if (e < EE) atomicAdd(&g_cnt[edst[e]], 1);
}

// ---------------- exclusive scan over g_cnt: shuffle-based, 1 block -------------
__global__ void k_scan() {
    __shared__ int wsum[32];
    __shared__ int carrysh;
    int tid = threadIdx.x, lane = tid & 31, wrp = tid >> 5;
    if (tid == 0) carrysh = 0;
    __syncthreads();
    for (int base = 0; base < NN; base += 1024) {
        int idx = base + tid;
        int v = (idx < NN) ? g_cnt[idx] : 0;
        // warp inclusive scan
        int x = v;
#pragma unroll
        for (int off = 1; off < 32; off <<= 1) {
            int t = __shfl_up_sync(0xffffffffu, x, off);
            if (lane >= off) x += t;
        }
        if (lane == 31) wsum[wrp] = x;
        __syncthreads();
        if (wrp == 0) {
            int w = (lane < 32) ? wsum[lane] : 0;
#pragma unroll
            for (int off = 1; off < 32; off <<= 1) {
                int t = __shfl_up_sync(0xffffffffu, w, off);
                if (lane >= off) w += t;
            }
            wsum[lane] = w;
        }
        __syncthreads();
        int warpbase = (wrp == 0) ? 0 : wsum[wrp - 1];
        int excl = carrysh + warpbase + x - v;
        if (idx < NN) { g_off[idx] = excl; g_cur[idx] = excl; }
        __syncthreads();
        if (tid == 0) carrysh += wsum[31];
        __syncthreads();
    }
    if (threadIdx.x == 0) g_off[NN] = carrysh;
}

__global__ void k_scatter(const int* __restrict__ esrc, const int* __restrict__ edst) {
    int e = blockIdx.x * blockDim.x + threadIdx.x;
    if (e < EE) {
        int p = atomicAdd(&g_cur[edst[e]], 1);
        g_pos[e] = p;
        g_srcp[p] = esrc[e];
    }
}

// ---------------- q = f0 @ Wq  (layer 0 only; later layers fused into k_agg) ------
__global__ void k_q(const float* __restrict__ Wq) {
    __shared__ float Wqs[CC * CC];
    int tid = threadIdx.x;
    for (int i = tid; i < CC * CC; i += blockDim.x) Wqs[i] = Wq[i];
    __syncthreads();
    int lane = tid & 31, wid = tid >> 5;
    int nwarp = gridDim.x * (blockDim.x >> 5);
    const float* f0 = g_f0[0];
    for (int n = blockIdx.x * (blockDim.x >> 5) + wid; n < NN; n += nwarp) {
        float v = f0[n * CC + lane];
        float acc = 0.f;
#pragma unroll
        for (int i = 0; i < CC; i++)
            acc = fmaf(__shfl_sync(0xffffffffu, v, i), Wqs[i * CC + lane], acc);
        g_q[n * CC + lane] = acc;
    }
}

// ---------------- edge pass: radial MLP, messages, attention logits ----------------
// warp handles exactly 8 edges; weights in smem, amortized over the 8-edge tile.
// Per-warp scratch: m0s aliases efs (live ranges serialized by the pipeline).
// Per-edge outputs stored at CSR slot g_pos[e] with streaming (evict-first) hints.
// FIRST=1: f1/f2 identically zero -> scalar {m0,u3,u5} streams only.
template <int FIRST>
__global__ __launch_bounds__(256)
void k_edge(int cur,
            const float* __restrict__ pos, const float* __restrict__ edge_feat,
            const int* __restrict__ esrc, const int* __restrict__ edst,
            const float* __restrict__ Wr1, const float* __restrict__ br1,
            const float* __restrict__ Wr2, const float* __restrict__ Wk) {
    extern __shared__ float sh[];
    float* Wr1s = sh;                       // 33*32
    float* br1s = Wr1s + 33 * CC;           // 32
    float* Wr2s = br1s + CC;                // 32*224
    float* Wks  = Wr2s + CC * PP * CC;      // 32*32
    float* wbase = Wks + CC * CC;

    int tid = threadIdx.x, lane = tid & 31, wid = tid >> 5;
    float* efs  = wbase + wid * 576;        // 8*32  (stage-1 input)
    float* m0s  = efs;                      // ALIAS: m0s live after efs dead
    float* hids = efs + 256;                // 8*32
    float* rels = hids + 256;               // 8*4
    int*   idxs = (int*)(rels + 32);        // 8*3 (src, dst, csr-slot)

    for (int i = tid; i < 33 * CC; i += blockDim.x) Wr1s[i] = Wr1[i];
    for (int i = tid; i < CC; i += blockDim.x) br1s[i] = br1[i];
    for (int i = tid; i < CC * PP * CC; i += blockDim.x) Wr2s[i] = Wr2[i];
    for (int i = tid; i < CC * CC; i += blockDim.x) Wks[i] = Wk[i];
    __syncthreads();

    const float*  f0  = g_f0[cur];
    const float4* f1  = g_f1[cur];
    const float4* f2  = g_f2[cur];
    const float*  f2b = g_f2b[cur];

    int nwarp = gridDim.x * (blockDim.x >> 5);
    int ntile = EE / EPW;
    for (int t = blockIdx.x * (blockDim.x >> 5) + wid; t < ntile; t += nwarp) {
        int base = t * EPW;
#pragma unroll
        for (int e8 = 0; e8 < EPW; e8++)
            efs[e8 * 32 + lane] = __ldcs(&edge_feat[(base + e8) * CC + lane]);
        if (lane < EPW) {
            int s = esrc[base + lane], d = edst[base + lane];
            idxs[lane * 3 + 0] = s;
            idxs[lane * 3 + 1] = d;
            idxs[lane * 3 + 2] = g_pos[base + lane];
            float rx = pos[d * 3 + 0] - pos[s * 3 + 0];
            float ry = pos[d * 3 + 1] - pos[s * 3 + 1];
            float rz = pos[d * 3 + 2] - pos[s * 3 + 2];
            rels[lane * 4 + 0] = rx; rels[lane * 4 + 1] = ry; rels[lane * 4 + 2] = rz;
            rels[lane * 4 + 3] = sqrtf(rx * rx + ry * ry + rz * rz + EPSF);
        }
        __syncwarp();

        // stage 1: hidden = relu([r, ef] @ Wr1 + br1)   (reads efs)
        float hid[EPW];
#pragma unroll
        for (int e8 = 0; e8 < EPW; e8++)
            hid[e8] = fmaf(rels[e8 * 4 + 3], Wr1s[lane], br1s[lane]);
#pragma unroll 4
        for (int i = 0; i < CC; i++) {
            float a1 = Wr1s[(i + 1) * CC + lane];
#pragma unroll
            for (int e8 = 0; e8 < EPW; e8++)
                hid[e8] = fmaf(efs[e8 * 32 + i], a1, hid[e8]);
        }
#pragma unroll
        for (int e8 = 0; e8 < EPW; e8++)
            hids[e8 * 32 + lane] = fmaxf(hid[e8], 0.f);
        __syncwarp();                       // efs dead from here

        // stage 2: w[e8][p] = hidden @ Wr2 (reshaped (P,C)), lane = channel
        float w[EPW][PP];
#pragma unroll
        for (int e8 = 0; e8 < EPW; e8++)
#pragma unroll
            for (int p = 0; p < PP; p++) w[e8][p] = 0.f;
        for (int i = 0; i < CC; i++) {
            float hv[EPW];
#pragma unroll
            for (int e8 = 0; e8 < EPW; e8++) hv[e8] = hids[e8 * 32 + i];
#pragma unroll
            for (int p = 0; p < PP; p++) {
                float r2 = Wr2s[i * (PP * CC) + p * CC + lane];
#pragma unroll
                for (int e8 = 0; e8 < EPW; e8++)
                    w[e8][p] = fmaf(hv[e8], r2, w[e8][p]);
            }
        }
        __syncwarp();                       // hids dead from here

        // per-edge messages -> CSR slots (fully unrolled: gathers front-batched)
#pragma unroll
        for (int e8 = 0; e8 < EPW; e8++) {
            int s = idxs[e8 * 3];
            int p = idxs[e8 * 3 + 2];
            float f0s = f0[s * CC + lane];
            if (FIRST) {
                float m0 = w[e8][0] * f0s;
                __stcs(&g_m0[p * CC + lane], m0);
                m0s[e8 * 32 + lane] = m0;
                __stcs(&g_u3[p * CC + lane], w[e8][3] * f0s);
                __stcs(&g_u5[p * CC + lane], w[e8][5] * f0s);
            } else {
                float rx = rels[e8 * 4], ry = rels[e8 * 4 + 1], rz = rels[e8 * 4 + 2];
                float r = rels[e8 * 4 + 3];
                float ir = 1.f / r;
                float ux = rx * ir, uy = ry * ir, uz = rz * ir;
                float Y2a = ux * uy, Y2b = uy * uz, Y2c = 3.f * uz * uz - 1.f;
                float Y2d = ux * uz, Y2e = ux * ux - uy * uy;
                float4 f1v = f1[s * CC + lane];
                float4 f2v = f2[s * CC + lane];
                float  f2e = f2b[s * CC + lane];
                float d1 = f1v.x * ux + f1v.y * uy + f1v.z * uz;
                float d2 = f2v.x * Y2a + f2v.y * Y2b + f2v.z * Y2c + f2v.w * Y2d + f2e * Y2e;
                float m0 = w[e8][0] * f0s + w[e8][1] * d1 + w[e8][2] * d2;
                m0s[e8 * 32 + lane] = m0;
                float4 pk;
                pk.x = m0;
                pk.y = w[e8][3] * f0s;
                pk.z = w[e8][5] * f0s;
                pk.w = w[e8][4];
                __stcs(&g_pk[p * CC + lane], pk);
                __stcs(&g_u6[p * CC + lane], w[e8][6]);
            }
        }
        __syncwarp();

        // k = m0 @ Wk, batched over the 8-edge tile
        float kk[EPW];
#pragma unroll
        for (int e8 = 0; e8 < EPW; e8++) kk[e8] = 0.f;
        for (int i = 0; i < CC; i++) {
            float wk = Wks[i * CC + lane];
#pragma unroll
            for (int e8 = 0; e8 < EPW; e8++)
                kk[e8] = fmaf(m0s[e8 * 32 + i], wk, kk[e8]);
        }

        // logits[e][h] = (q[dst] . k) per 8-lane head group / sqrt(8)
#pragma unroll
        for (int e8 = 0; e8 < EPW; e8++) {
            int d = idxs[e8 * 3 + 1];
            int p = idxs[e8 * 3 + 2];
            float tt = g_q[d * CC + lane] * kk[e8];
            tt += __shfl_xor_sync(0xffffffffu, tt, 4);
            tt += __shfl_xor_sync(0xffffffffu, tt, 2);
            tt += __shfl_xor_sync(0xffffffffu, tt, 1);
            if ((lane & 7) == 0)
                g_logit[p * HH + (lane >> 3)] = tt * 0.35355339059327373f;
        }
        __syncwarp();
    }
}

// ---------------- aggregation + softmax + self/skip update (warp per node) ----------------
// All per-edge arrays are in CSR order: fully sequential streams, read with
// streaming hints (single use). f0/f1/f2/pos gathers use the default policy (reused).
// Wq != nullptr: fuse q = f0_new @ Wq for the next layer.
template <int FIRST>
__global__ __launch_bounds__(256)
void k_agg(int cur,
           const float* __restrict__ pos,
           const float* __restrict__ W0, const float* __restrict__ W1,
           const float* __restrict__ W2, const float* __restrict__ Wsk,
           const float* __restrict__ Wq) {
    __shared__ float W0s[CC * CC], W1s[CC * CC], W2s[CC * CC], Wsks[CC * CC], Wqs[CC * CC];
    __shared__ float st[8][320];
    int tid = threadIdx.x;
    for (int i = tid; i < CC * CC; i += blockDim.x) {
        W0s[i] = W0[i]; W1s[i] = W1[i]; W2s[i] = W2[i]; Wsks[i] = Wsk[i];
        if (Wq) Wqs[i] = Wq[i];
    }
    __syncthreads();
    int lane = tid & 31, wid = tid >> 5;
    int h = lane >> 3;
    const float*  f0  = g_f0[cur];
    const float4* f1  = g_f1[cur];
    const float4* f2  = g_f2[cur];
    const float*  f2b = g_f2b[cur];
    float*  f0o  = g_f0[cur ^ 1];
    float4* f1o  = g_f1[cur ^ 1];
    float4* f2o  = g_f2[cur ^ 1];
    float*  f2bo = g_f2b[cur ^ 1];
    int nwarp = gridDim.x * 8;
    for (int n = blockIdx.x * 8 + wid; n < NN; n += nwarp) {
        int j0 = g_off[n], j1 = g_off[n + 1];
        float px = pos[n * 3], py = pos[n * 3 + 1], pz = pos[n * 3 + 2];
        float mx = -3.4e38f;
        for (int j = j0; j < j1; j++)
            mx = fmaxf(mx, g_logit[j * HH + h]);
        float a0 = 0, a10 = 0, a11 = 0, a12 = 0;
        float a20 = 0, a21 = 0, a22 = 0, a23 = 0, a24 = 0, den = 0;
#pragma unroll 2
        for (int j = j0; j < j1; j++) {
            float ex = __expf(__ldcs(&g_logit[j * HH + h]) - mx);
            den += ex;
            int s = g_srcp[j];
            float rx = px - pos[s * 3], ry = py - pos[s * 3 + 1], rz = pz - pos[s * 3 + 2];
            float r = sqrtf(rx * rx + ry * ry + rz * rz + EPSF);
            float ir = 1.f / r;
            float ux = rx * ir, uy = ry * ir, uz = rz * ir;
            float Y2a = ux * uy, Y2b = uy * uz, Y2c = 3.f * uz * uz - 1.f;
            float Y2d = ux * uz, Y2e = ux * ux - uy * uy;
            if (FIRST) {
                float m0 = __ldcs(&g_m0[j * CC + lane]);
                float u3 = __ldcs(&g_u3[j * CC + lane]);
                float u5 = __ldcs(&g_u5[j * CC + lane]);
                a0 = fmaf(ex, m0, a0);
                float exu3 = ex * u3, exu5 = ex * u5;
                a10 = fmaf(exu3, ux, a10);
                a11 = fmaf(exu3, uy, a11);
                a12 = fmaf(exu3, uz, a12);
                a20 = fmaf(exu5, Y2a, a20);
                a21 = fmaf(exu5, Y2b, a21);
                a22 = fmaf(exu5, Y2c, a22);
                a23 = fmaf(exu5, Y2d, a23);
                a24 = fmaf(exu5, Y2e, a24);
            } else {
                float4 pk = __ldcs(&g_pk[j * CC + lane]);   // {m0,u3,u5,u4}
                float  u6 = __ldcs(&g_u6[j * CC + lane]);
                float4 f1v = f1[s * CC + lane];
                float4 f2v = f2[s * CC + lane];
                float  f2e = f2b[s * CC + lane];
                a0 = fmaf(ex, pk.x, a0);
                a10 = fmaf(ex, fmaf(pk.y, ux, pk.w * f1v.x), a10);
                a11 = fmaf(ex, fmaf(pk.y, uy, pk.w * f1v.y), a11);
                a12 = fmaf(ex, fmaf(pk.y, uz, pk.w * f1v.z), a12);
                a20 = fmaf(ex, fmaf(pk.z, Y2a, u6 * f2v.x), a20);
                a21 = fmaf(ex, fmaf(pk.z, Y2b, u6 * f2v.y), a21);
                a22 = fmaf(ex, fmaf(pk.z, Y2c, u6 * f2v.z), a22);
                a23 = fmaf(ex, fmaf(pk.z, Y2d, u6 * f2v.w), a23);
                a24 = fmaf(ex, fmaf(pk.z, Y2e, u6 * f2e), a24);
            }
        }
        float sc = 1.f / (den + EPSF);
        float* sp = &st[wid][lane * 10];
        sp[0] = a0 * sc;
        sp[1] = a10 * sc; sp[2] = a11 * sc; sp[3] = a12 * sc;
        sp[4] = a20 * sc; sp[5] = a21 * sc; sp[6] = a22 * sc;
        sp[7] = a23 * sc; sp[8] = a24 * sc;
        sp[9] = f0[n * CC + lane];
        __syncwarp();
        float o0 = 0, o10 = 0, o11 = 0, o12 = 0;
        float o20 = 0, o21 = 0, o22 = 0, o23 = 0, o24 = 0;
#pragma unroll 8
        for (int i = 0; i < CC; i++) {
            const float* q = &st[wid][i * 10];
            float w0 = W0s[i * CC + lane], wk = Wsks[i * CC + lane];
            float w1 = W1s[i * CC + lane], w2 = W2s[i * CC + lane];
            o0 = fmaf(q[0], w0, fmaf(q[9], wk, o0));
            o10 = fmaf(q[1], w1, o10); o11 = fmaf(q[2], w1, o11); o12 = fmaf(q[3], w1, o12);
            o20 = fmaf(q[4], w2, o20); o21 = fmaf(q[5], w2, o21);
            o22 = fmaf(q[6], w2, o22); o23 = fmaf(q[7], w2, o23); o24 = fmaf(q[8], w2, o24);
        }
        f0o[n * CC + lane] = o0;
        f1o[n * CC + lane] = make_float4(o10, o11, o12, 0.f);
        f2o[n * CC + lane] = make_float4(o20, o21, o22, o23);
        f2bo[n * CC + lane] = o24;
        __syncwarp();
        // fused q = f0_new @ Wq for the next layer
        if (Wq) {
            float qa = 0.f;
#pragma unroll
            for (int i = 0; i < CC; i++)
                qa = fmaf(__shfl_sync(0xffffffffu, o0, i), Wqs[i * CC + lane], qa);
            g_q[n * CC + lane] = qa;
        }
        __syncwarp();
    }
}

// ---------------- output head: hs0 = f0 @ Wout, cs = hs0 @ Wc ----------------
__global__ void k_out(int cur, const float* __restrict__ Wout,
                      const float* __restrict__ Wc, float* __restrict__ out) {
    __shared__ float Wos[CC * CC];
    __shared__ float Wcs[CC * NTT];
    __shared__ float hsm[8][32];
    int tid = threadIdx.x;
    for (int i = tid; i < CC * CC; i += blockDim.x) Wos[i] = Wout[i];
    for (int i = tid; i < CC * NTT; i += blockDim.x) Wcs[i] = Wc[i];
    __syncthreads();
    int lane = tid & 31, wid = tid >> 5;
    const float* f0 = g_f0[cur];
    int nwarp = gridDim.x * 8;
    for (int n = blockIdx.x * 8 + wid; n < NN; n += nwarp) {
        float v = f0[n * CC + lane];
        float hacc = 0.f;
#pragma unroll
        for (int i = 0; i < CC; i++)
            hacc = fmaf(__shfl_sync(0xffffffffu, v, i), Wos[i * CC + lane], hacc);
        out[n * CC + lane] = hacc;
        hsm[wid][lane] = hacc;
        __syncwarp();
        if (lane < NTT) {
            float c = 0.f;
#pragma unroll
            for (int o = 0; o < CC; o++)
                c = fmaf(hsm[wid][o], Wcs[o * NTT + lane], c);
            out[NN * CC + n * NTT + lane] = c;
        }
        __syncwarp();
    }
}

// ---------------- launch ----------------
extern "C" void kernel_launch(void* const* d_in, const int* in_sizes, int n_in,
                              void* d_out, int out_size) {
    const float* pos       = (const float*)d_in[0];
    const float* node_l0   = (const float*)d_in[1];
    const float* edge_feat = (const float*)d_in[2];
    const int*   esrc      = (const int*)d_in[3];
    const int*   edst      = (const int*)d_in[4];
    const float* Wr1 = (const float*)d_in[5];
    const float* br1 = (const float*)d_in[6];
    const float* Wr2 = (const float*)d_in[7];
    const float* Wq  = (const float*)d_in[8];
    const float* Wk  = (const float*)d_in[9];
    const float* Ws0 = (const float*)d_in[10];
    const float* Ws1 = (const float*)d_in[11];
    const float* Ws2 = (const float*)d_in[12];
    const float* Wsk = (const float*)d_in[13];
    const float* Wout = (const float*)d_in[14];
    const float* Wc   = (const float*)d_in[15];
    float* out = (float*)d_out;

    int smem_edge = (33 * CC + CC + CC * PP * CC + CC * CC + 8 * 576) * (int)sizeof(float);
    cudaFuncSetAttribute(k_edge<0>, cudaFuncAttributeMaxDynamicSharedMemorySize, smem_edge);
    cudaFuncSetAttribute(k_edge<1>, cudaFuncAttributeMaxDynamicSharedMemorySize, smem_edge);

    k_init<<<(NN * CC + 255) / 256, 256>>>(node_l0, edst);
    k_count<<<(EE + 255) / 256, 256>>>(edst);
    k_scan<<<1, 1024>>>();
    k_scatter<<<(EE + 255) / 256, 256>>>(esrc, edst);

    // layer 0 (f1 = f2 = 0 specialization)
    k_q<<<1184, 256>>>(Wq);
    k_edge<1><<<456, 256, smem_edge>>>(0, pos, edge_feat, esrc, edst,
                                       Wr1, br1, Wr2, Wk);
    k_agg<1><<<1184, 256>>>(0, pos, Ws0, Ws1, Ws2, Wsk, Wq + CC * CC);

    // layer 1
    k_edge<0><<<456, 256, smem_edge>>>(1, pos, edge_feat, esrc, edst,
                                       Wr1 + 33 * CC, br1 + CC,
                                       Wr2 + CC * PP * CC, Wk + CC * CC);
    k_agg<0><<<1184, 256>>>(1, pos,
                            Ws0 + CC * CC, Ws1 + CC * CC,
                            Ws2 + CC * CC, Wsk + CC * CC, (const float*)0);

    k_out<<<1184, 256>>>(0, Wout, Wc, out);
}

// round 15
// speedup vs baseline: 1.1172x; 1.1172x over previous
#include <cuda_runtime.h>

#define NN 30000
#define EE 480000
#define CC 32
#define LL 2
#define PP 7
#define HH 4
#define NTT 15
#define EPSF 1e-8f
#define EPW 8

static_assert(EE % EPW == 0, "edge tiles are exact");

typedef unsigned long long ull;

// packed f32x2 helpers (SASS FFMA2 path; only reachable via PTX)
__device__ __forceinline__ ull pack2f(float a, float b) {
    ull r; asm("mov.b64 %0, {%1, %2};" : "=l"(r) : "f"(a), "f"(b)); return r;
}
__device__ __forceinline__ ull dup2f(float a) { return pack2f(a, a); }
__device__ __forceinline__ ull fma2f(ull a, ull b, ull c) {
    ull d; asm("fma.rn.f32x2 %0, %1, %2, %3;" : "=l"(d) : "l"(a), "l"(b), "l"(c)); return d;
}
__device__ __forceinline__ float2 unpk2(ull v) {
    float2 r; asm("mov.b64 {%0, %1}, %2;" : "=f"(r.x), "=f"(r.y) : "l"(v)); return r;
}

// ---------------- static device scratch (no allocation allowed) ----------------
__device__ float  g_f0[2][NN * CC];
__device__ float4 g_f1[2][NN * CC];        // {x,y,z,pad}
__device__ float4 g_f2[2][NN * CC];        // components 0..3
__device__ float  g_f2b[2][NN * CC];       // component 4
__device__ float  g_q[NN * CC];
// per-edge data stored in CSR (dst-sorted) order:
__device__ float  g_m0[EE * CC];           // layer-0 streams
__device__ float  g_u3[EE * CC];
__device__ float  g_u5[EE * CC];
__device__ float4 g_pk[EE * CC];           // layer-1 packed {m0,u3,u5,u4}
__device__ float  g_u6[EE * CC];
__device__ float  g_logit[EE * HH];
__device__ int g_srcp[EE];      // src node id, CSR order
__device__ int g_pos[EE];       // edge -> CSR slot
__device__ int g_cnt[NN + 1];
__device__ int g_off[NN + 1];
__device__ int g_cur[NN];

// ---------------- init: f0 <- node_l0, cnt <- 0 ----------------
__global__ void k_init(const float* __restrict__ node_l0) {
    int i = blockIdx.x * blockDim.x + threadIdx.x;
    if (i < NN * CC) g_f0[0][i] = node_l0[i];
    if (i <= NN) g_cnt[i] = 0;
}

__global__ void k_count(const int* __restrict__ edst) {
    int e = blockIdx.x * blockDim.x + threadIdx.x;
    if (e < EE) atomicAdd(&g_cnt[edst[e]], 1);
}

// ---------------- exclusive scan over g_cnt: shuffle-based, 1 block -------------
__global__ void k_scan() {
    __shared__ int wsum[32];
    __shared__ int carrysh;
    int tid = threadIdx.x, lane = tid & 31, wrp = tid >> 5;
    if (tid == 0) carrysh = 0;
    __syncthreads();
    for (int base = 0; base < NN; base += 1024) {
        int idx = base + tid;
        int v = (idx < NN) ? g_cnt[idx] : 0;
        int x = v;
#pragma unroll
        for (int off = 1; off < 32; off <<= 1) {
            int t = __shfl_up_sync(0xffffffffu, x, off);
            if (lane >= off) x += t;
        }
        if (lane == 31) wsum[wrp] = x;
        __syncthreads();
        if (wrp == 0) {
            int w = wsum[lane];
#pragma unroll
            for (int off = 1; off < 32; off <<= 1) {
                int t = __shfl_up_sync(0xffffffffu, w, off);
                if (lane >= off) w += t;
            }
            wsum[lane] = w;
        }
        __syncthreads();
        int warpbase = (wrp == 0) ? 0 : wsum[wrp - 1];
        int excl = carrysh + warpbase + x - v;
        if (idx < NN) { g_off[idx] = excl; g_cur[idx] = excl; }
        __syncthreads();
        if (tid == 0) carrysh += wsum[31];
        __syncthreads();
    }
    if (threadIdx.x == 0) g_off[NN] = carrysh;
}

__global__ void k_scatter(const int* __restrict__ esrc, const int* __restrict__ edst) {
    int e = blockIdx.x * blockDim.x + threadIdx.x;
    if (e < EE) {
        int p = atomicAdd(&g_cur[edst[e]], 1);
        g_pos[e] = p;
        g_srcp[p] = esrc[e];
    }
}

// ---------------- q = f0 @ Wq  (layer 0 only; later layers fused into k_agg) ------
__global__ void k_q(const float* __restrict__ Wq) {
    __shared__ float Wqs[CC * CC];
    int tid = threadIdx.x;
    for (int i = tid; i < CC * CC; i += blockDim.x) Wqs[i] = Wq[i];
    __syncthreads();
    int lane = tid & 31, wid = tid >> 5;
    int nwarp = gridDim.x * (blockDim.x >> 5);
    const float* f0 = g_f0[0];
    for (int n = blockIdx.x * (blockDim.x >> 5) + wid; n < NN; n += nwarp) {
        float v = f0[n * CC + lane];
        float acc = 0.f;
#pragma unroll
        for (int i = 0; i < CC; i++)
            acc = fmaf(__shfl_sync(0xffffffffu, v, i), Wqs[i * CC + lane], acc);
        g_q[n * CC + lane] = acc;
    }
}

// ---------------- edge pass: radial MLP, messages, attention logits ----------------
// warp handles exactly 8 edges packed into 4 f32x2 pairs (FFMA2 path).
// Scratch transposed to [i*8+e8] so packed operands are broadcast LDS.64s.
// Per-edge outputs stored at CSR slot g_pos[e] with streaming hints.
template <int FIRST>
__global__ __launch_bounds__(256)
void k_edge(int cur,
            const float* __restrict__ pos, const float* __restrict__ edge_feat,
            const int* __restrict__ esrc, const int* __restrict__ edst,
            const float* __restrict__ Wr1, const float* __restrict__ br1,
            const float* __restrict__ Wr2, const float* __restrict__ Wk) {
    extern __shared__ float sh[];
    float* Wr1s = sh;                       // 33*32
    float* br1s = Wr1s + 33 * CC;           // 32
    float* Wr2s = br1s + CC;                // 32*224
    float* Wks  = Wr2s + CC * PP * CC;      // 32*32
    float* wbase = Wks + CC * CC;

    int tid = threadIdx.x, lane = tid & 31, wid = tid >> 5;
    float* efs  = wbase + wid * 576;        // [i*8+e8] stage-1 input (transposed)
    float* m0t  = efs;                      // ALIAS: m0t live after efs dead
    float* hidt = efs + 256;                // [i*8+e8] hidden (transposed)
    float* rels = hidt + 256;               // 8*4
    int*   idxs = (int*)(rels + 32);        // 8*3 (src, dst, csr-slot)

    for (int i = tid; i < 33 * CC; i += blockDim.x) Wr1s[i] = Wr1[i];
    for (int i = tid; i < CC; i += blockDim.x) br1s[i] = br1[i];
    for (int i = tid; i < CC * PP * CC; i += blockDim.x) Wr2s[i] = Wr2[i];
    for (int i = tid; i < CC * CC; i += blockDim.x) Wks[i] = Wk[i];
    __syncthreads();

    const float*  f0  = g_f0[cur];
    const float4* f1  = g_f1[cur];
    const float4* f2  = g_f2[cur];
    const float*  f2b = g_f2b[cur];

    int nwarp = gridDim.x * (blockDim.x >> 5);
    int ntile = EE / EPW;
    for (int t = blockIdx.x * (blockDim.x >> 5) + wid; t < ntile; t += nwarp) {
        int base = t * EPW;
        // load edge features, write transposed [lane*8+e8]
        float ef[EPW];
#pragma unroll
        for (int e8 = 0; e8 < EPW; e8++)
            ef[e8] = __ldcs(&edge_feat[(base + e8) * CC + lane]);
#pragma unroll
        for (int j = 0; j < 4; j++)
            *(float2*)&efs[lane * 8 + 2 * j] = make_float2(ef[2 * j], ef[2 * j + 1]);
        if (lane < EPW) {
            int s = esrc[base + lane], d = edst[base + lane];
            idxs[lane * 3 + 0] = s;
            idxs[lane * 3 + 1] = d;
            idxs[lane * 3 + 2] = g_pos[base + lane];
            float rx = pos[d * 3 + 0] - pos[s * 3 + 0];
            float ry = pos[d * 3 + 1] - pos[s * 3 + 1];
            float rz = pos[d * 3 + 2] - pos[s * 3 + 2];
            rels[lane * 4 + 0] = rx; rels[lane * 4 + 1] = ry; rels[lane * 4 + 2] = rz;
            rels[lane * 4 + 3] = sqrtf(rx * rx + ry * ry + rz * rz + EPSF);
        }
        __syncwarp();

        // stage 1 (packed): hidden = relu([r, ef] @ Wr1 + br1)
        ull hid2[4];
        {
            ull w0d = dup2f(Wr1s[lane]);
            ull b0d = dup2f(br1s[lane]);
#pragma unroll
            for (int j = 0; j < 4; j++)
                hid2[j] = fma2f(pack2f(rels[(2 * j) * 4 + 3], rels[(2 * j + 1) * 4 + 3]), w0d, b0d);
        }
#pragma unroll 4
        for (int i = 0; i < CC; i++) {
            ull a1 = dup2f(Wr1s[(i + 1) * CC + lane]);
#pragma unroll
            for (int j = 0; j < 4; j++)
                hid2[j] = fma2f(*(const ull*)&efs[i * 8 + 2 * j], a1, hid2[j]);
        }
#pragma unroll
        for (int j = 0; j < 4; j++) {
            float2 hv = unpk2(hid2[j]);
            *(float2*)&hidt[lane * 8 + 2 * j] =
                make_float2(fmaxf(hv.x, 0.f), fmaxf(hv.y, 0.f));
        }
        __syncwarp();                       // efs dead from here

        // stage 2 (packed): w[e8][p] = hidden @ Wr2, lane = channel
        ull w2[4][PP] = {};
        for (int i = 0; i < CC; i++) {
            ull hv2[4];
#pragma unroll
            for (int j = 0; j < 4; j++)
                hv2[j] = *(const ull*)&hidt[i * 8 + 2 * j];
#pragma unroll
            for (int p = 0; p < PP; p++) {
                ull r2d = dup2f(Wr2s[i * (PP * CC) + p * CC + lane]);
#pragma unroll
                for (int j = 0; j < 4; j++)
                    w2[j][p] = fma2f(hv2[j], r2d, w2[j][p]);
            }
        }
        __syncwarp();                       // hidt dead from here

        // per-edge messages -> CSR slots (fully unrolled: gathers front-batched)
        float m0r[EPW];
#pragma unroll
        for (int e8 = 0; e8 < EPW; e8++) {
            int s = idxs[e8 * 3];
            int p = idxs[e8 * 3 + 2];
            float f0s = f0[s * CC + lane];
            int jj = e8 >> 1, hh = e8 & 1;
            float2 w0p = unpk2(w2[jj][0]);
            float2 w3p = unpk2(w2[jj][3]);
            float2 w5p = unpk2(w2[jj][5]);
            float w0v = hh ? w0p.y : w0p.x;
            float w3v = hh ? w3p.y : w3p.x;
            float w5v = hh ? w5p.y : w5p.x;
            if (FIRST) {
                float m0 = w0v * f0s;
                __stcs(&g_m0[p * CC + lane], m0);
                m0r[e8] = m0;
                __stcs(&g_u3[p * CC + lane], w3v * f0s);
                __stcs(&g_u5[p * CC + lane], w5v * f0s);
            } else {
                float2 w1p = unpk2(w2[jj][1]);
                float2 w2p = unpk2(w2[jj][2]);
                float2 w4p = unpk2(w2[jj][4]);
                float2 w6p = unpk2(w2[jj][6]);
                float w1v = hh ? w1p.y : w1p.x;
                float w2v = hh ? w2p.y : w2p.x;
                float w4v = hh ? w4p.y : w4p.x;
                float w6v = hh ? w6p.y : w6p.x;
                float rx = rels[e8 * 4], ry = rels[e8 * 4 + 1], rz = rels[e8 * 4 + 2];
                float r = rels[e8 * 4 + 3];
                float ir = 1.f / r;
                float ux = rx * ir, uy = ry * ir, uz = rz * ir;
                float Y2a = ux * uy, Y2b = uy * uz, Y2c = 3.f * uz * uz - 1.f;
                float Y2d = ux * uz, Y2e = ux * ux - uy * uy;
                float4 f1v = f1[s * CC + lane];
                float4 f2v = f2[s * CC + lane];
                float  f2e = f2b[s * CC + lane];
                float d1 = f1v.x * ux + f1v.y * uy + f1v.z * uz;
                float d2 = f2v.x * Y2a + f2v.y * Y2b + f2v.z * Y2c + f2v.w * Y2d + f2e * Y2e;
                float m0 = w0v * f0s + w1v * d1 + w2v * d2;
                m0r[e8] = m0;
                float4 pk;
                pk.x = m0;
                pk.y = w3v * f0s;
                pk.z = w5v * f0s;
                pk.w = w4v;
                __stcs(&g_pk[p * CC + lane], pk);
                __stcs(&g_u6[p * CC + lane], w6v);
            }
        }
        // store m0 transposed [lane*8+e8] for the packed Wk loop
#pragma unroll
        for (int j = 0; j < 4; j++)
            *(float2*)&m0t[lane * 8 + 2 * j] = make_float2(m0r[2 * j], m0r[2 * j + 1]);
        __syncwarp();

        // k = m0 @ Wk (packed over the 4 edge-pairs)
        ull kk2[4] = {};
        for (int i = 0; i < CC; i++) {
            ull wkd = dup2f(Wks[i * CC + lane]);
#pragma unroll
            for (int j = 0; j < 4; j++)
                kk2[j] = fma2f(*(const ull*)&m0t[i * 8 + 2 * j], wkd, kk2[j]);
        }
        float kk[EPW];
#pragma unroll
        for (int j = 0; j < 4; j++) {
            float2 kv = unpk2(kk2[j]);
            kk[2 * j] = kv.x; kk[2 * j + 1] = kv.y;
        }

        // logits[e][h] = (q[dst] . k) per 8-lane head group / sqrt(8)
#pragma unroll
        for (int e8 = 0; e8 < EPW; e8++) {
            int d = idxs[e8 * 3 + 1];
            int p = idxs[e8 * 3 + 2];
            float tt = g_q[d * CC + lane] * kk[e8];
            tt += __shfl_xor_sync(0xffffffffu, tt, 4);
            tt += __shfl_xor_sync(0xffffffffu, tt, 2);
            tt += __shfl_xor_sync(0xffffffffu, tt, 1);
            if ((lane & 7) == 0)
                g_logit[p * HH + (lane >> 3)] = tt * 0.35355339059327373f;
        }
        __syncwarp();
    }
}

// ---------------- aggregation + softmax + self/skip update (warp per node) ----------------
template <int FIRST>
__global__ __launch_bounds__(256)
void k_agg(int cur,
           const float* __restrict__ pos,
           const float* __restrict__ W0, const float* __restrict__ W1,
           const float* __restrict__ W2, const float* __restrict__ Wsk,
           const float* __restrict__ Wq) {
    __shared__ float W0s[CC * CC], W1s[CC * CC], W2s[CC * CC], Wsks[CC * CC], Wqs[CC * CC];
    __shared__ float st[8][320];
    int tid = threadIdx.x;
    for (int i = tid; i < CC * CC; i += blockDim.x) {
        W0s[i] = W0[i]; W1s[i] = W1[i]; W2s[i] = W2[i]; Wsks[i] = Wsk[i];
        if (Wq) Wqs[i] = Wq[i];
    }
    __syncthreads();
    int lane = tid & 31, wid = tid >> 5;
    int h = lane >> 3;
    const float*  f0  = g_f0[cur];
    const float4* f1  = g_f1[cur];
    const float4* f2  = g_f2[cur];
    const float*  f2b = g_f2b[cur];
    float*  f0o  = g_f0[cur ^ 1];
    float4* f1o  = g_f1[cur ^ 1];
    float4* f2o  = g_f2[cur ^ 1];
    float*  f2bo = g_f2b[cur ^ 1];
    int nwarp = gridDim.x * 8;
    for (int n = blockIdx.x * 8 + wid; n < NN; n += nwarp) {
        int j0 = g_off[n], j1 = g_off[n + 1];
        float px = pos[n * 3], py = pos[n * 3 + 1], pz = pos[n * 3 + 2];
        float mx = -3.4e38f;
        for (int j = j0; j < j1; j++)
            mx = fmaxf(mx, g_logit[j * HH + h]);
        float a0 = 0, a10 = 0, a11 = 0, a12 = 0;
        float a20 = 0, a21 = 0, a22 = 0, a23 = 0, a24 = 0, den = 0;
#pragma unroll 2
        for (int j = j0; j < j1; j++) {
            float ex = __expf(__ldcs(&g_logit[j * HH + h]) - mx);
            den += ex;
            int s = g_srcp[j];
            float rx = px - pos[s * 3], ry = py - pos[s * 3 + 1], rz = pz - pos[s * 3 + 2];
            float r = sqrtf(rx * rx + ry * ry + rz * rz + EPSF);
            float ir = 1.f / r;
            float ux = rx * ir, uy = ry * ir, uz = rz * ir;
            float Y2a = ux * uy, Y2b = uy * uz, Y2c = 3.f * uz * uz - 1.f;
            float Y2d = ux * uz, Y2e = ux * ux - uy * uy;
            if (FIRST) {
                float m0 = __ldcs(&g_m0[j * CC + lane]);
                float u3 = __ldcs(&g_u3[j * CC + lane]);
                float u5 = __ldcs(&g_u5[j * CC + lane]);
                a0 = fmaf(ex, m0, a0);
                float exu3 = ex * u3, exu5 = ex * u5;
                a10 = fmaf(exu3, ux, a10);
                a11 = fmaf(exu3, uy, a11);
                a12 = fmaf(exu3, uz, a12);
                a20 = fmaf(exu5, Y2a, a20);
                a21 = fmaf(exu5, Y2b, a21);
                a22 = fmaf(exu5, Y2c, a22);
                a23 = fmaf(exu5, Y2d, a23);
                a24 = fmaf(exu5, Y2e, a24);
            } else {
                float4 pk = __ldcs(&g_pk[j * CC + lane]);   // {m0,u3,u5,u4}
                float  u6 = __ldcs(&g_u6[j * CC + lane]);
                float4 f1v = f1[s * CC + lane];
                float4 f2v = f2[s * CC + lane];
                float  f2e = f2b[s * CC + lane];
                a0 = fmaf(ex, pk.x, a0);
                a10 = fmaf(ex, fmaf(pk.y, ux, pk.w * f1v.x), a10);
                a11 = fmaf(ex, fmaf(pk.y, uy, pk.w * f1v.y), a11);
                a12 = fmaf(ex, fmaf(pk.y, uz, pk.w * f1v.z), a12);
                a20 = fmaf(ex, fmaf(pk.z, Y2a, u6 * f2v.x), a20);
                a21 = fmaf(ex, fmaf(pk.z, Y2b, u6 * f2v.y), a21);
                a22 = fmaf(ex, fmaf(pk.z, Y2c, u6 * f2v.z), a22);
                a23 = fmaf(ex, fmaf(pk.z, Y2d, u6 * f2v.w), a23);
                a24 = fmaf(ex, fmaf(pk.z, Y2e, u6 * f2e), a24);
            }
        }
        float sc = 1.f / (den + EPSF);
        float* sp = &st[wid][lane * 10];
        sp[0] = a0 * sc;
        sp[1] = a10 * sc; sp[2] = a11 * sc; sp[3] = a12 * sc;
        sp[4] = a20 * sc; sp[5] = a21 * sc; sp[6] = a22 * sc;
        sp[7] = a23 * sc; sp[8] = a24 * sc;
        sp[9] = f0[n * CC + lane];
        __syncwarp();
        float o0 = 0, o10 = 0, o11 = 0, o12 = 0;
        float o20 = 0, o21 = 0, o22 = 0, o23 = 0, o24 = 0;
#pragma unroll 8
        for (int i = 0; i < CC; i++) {
            const float* q = &st[wid][i * 10];
            float w0 = W0s[i * CC + lane], wk = Wsks[i * CC + lane];
            float w1 = W1s[i * CC + lane], w2 = W2s[i * CC + lane];
            o0 = fmaf(q[0], w0, fmaf(q[9], wk, o0));
            o10 = fmaf(q[1], w1, o10); o11 = fmaf(q[2], w1, o11); o12 = fmaf(q[3], w1, o12);
            o20 = fmaf(q[4], w2, o20); o21 = fmaf(q[5], w2, o21);
            o22 = fmaf(q[6], w2, o22); o23 = fmaf(q[7], w2, o23); o24 = fmaf(q[8], w2, o24);
        }
        f0o[n * CC + lane] = o0;
        f1o[n * CC + lane] = make_float4(o10, o11, o12, 0.f);
        f2o[n * CC + lane] = make_float4(o20, o21, o22, o23);
        f2bo[n * CC + lane] = o24;
        __syncwarp();
        // fused q = f0_new @ Wq for the next layer
        if (Wq) {
            float qa = 0.f;
#pragma unroll
            for (int i = 0; i < CC; i++)
                qa = fmaf(__shfl_sync(0xffffffffu, o0, i), Wqs[i * CC + lane], qa);
            g_q[n * CC + lane] = qa;
        }
        __syncwarp();
    }
}

// ---------------- output head: hs0 = f0 @ Wout, cs = hs0 @ Wc ----------------
__global__ void k_out(int cur, const float* __restrict__ Wout,
                      const float* __restrict__ Wc, float* __restrict__ out) {
    __shared__ float Wos[CC * CC];
    __shared__ float Wcs[CC * NTT];
    __shared__ float hsm[8][32];
    int tid = threadIdx.x;
    for (int i = tid; i < CC * CC; i += blockDim.x) Wos[i] = Wout[i];
    for (int i = tid; i < CC * NTT; i += blockDim.x) Wcs[i] = Wc[i];
    __syncthreads();
    int lane = tid & 31, wid = tid >> 5;
    const float* f0 = g_f0[cur];
    int nwarp = gridDim.x * 8;
    for (int n = blockIdx.x * 8 + wid; n < NN; n += nwarp) {
        float v = f0[n * CC + lane];
        float hacc = 0.f;
#pragma unroll
        for (int i = 0; i < CC; i++)
            hacc = fmaf(__shfl_sync(0xffffffffu, v, i), Wos[i * CC + lane], hacc);
        out[n * CC + lane] = hacc;
        hsm[wid][lane] = hacc;
        __syncwarp();
        if (lane < NTT) {
            float c = 0.f;
#pragma unroll
            for (int o = 0; o < CC; o++)
                c = fmaf(hsm[wid][o], Wcs[o * NTT + lane], c);
            out[NN * CC + n * NTT + lane] = c;
        }
        __syncwarp();
    }
}

// ---------------- launch ----------------
extern "C" void kernel_launch(void* const* d_in, const int* in_sizes, int n_in,
                              void* d_out, int out_size) {
    const float* pos       = (const float*)d_in[0];
    const float* node_l0   = (const float*)d_in[1];
    const float* edge_feat = (const float*)d_in[2];
    const int*   esrc      = (const int*)d_in[3];
    const int*   edst      = (const int*)d_in[4];
    const float* Wr1 = (const float*)d_in[5];
    const float* br1 = (const float*)d_in[6];
    const float* Wr2 = (const float*)d_in[7];
    const float* Wq  = (const float*)d_in[8];
    const float* Wk  = (const float*)d_in[9];
    const float* Ws0 = (const float*)d_in[10];
    const float* Ws1 = (const float*)d_in[11];
    const float* Ws2 = (const float*)d_in[12];
    const float* Wsk = (const float*)d_in[13];
    const float* Wout = (const float*)d_in[14];
    const float* Wc   = (const float*)d_in[15];
    float* out = (float*)d_out;

    int smem_edge = (33 * CC + CC + CC * PP * CC + CC * CC + 8 * 576) * (int)sizeof(float);
    cudaFuncSetAttribute(k_edge<0>, cudaFuncAttributeMaxDynamicSharedMemorySize, smem_edge);
    cudaFuncSetAttribute(k_edge<1>, cudaFuncAttributeMaxDynamicSharedMemorySize, smem_edge);

    k_init<<<(NN * CC + 255) / 256, 256>>>(node_l0);
    k_count<<<(EE + 255) / 256, 256>>>(edst);
    k_scan<<<1, 1024>>>();
    k_scatter<<<(EE + 255) / 256, 256>>>(esrc, edst);

    // layer 0 (f1 = f2 = 0 specialization)
    k_q<<<1184, 256>>>(Wq);
    k_edge<1><<<456, 256, smem_edge>>>(0, pos, edge_feat, esrc, edst,
                                       Wr1, br1, Wr2, Wk);
    k_agg<1><<<1184, 256>>>(0, pos, Ws0, Ws1, Ws2, Wsk, Wq + CC * CC);

    // layer 1
    k_edge<0><<<456, 256, smem_edge>>>(1, pos, edge_feat, esrc, edst,
                                       Wr1 + 33 * CC, br1 + CC,
                                       Wr2 + CC * PP * CC, Wk + CC * CC);
    k_agg<0><<<1184, 256>>>(1, pos,
                            Ws0 + CC * CC, Ws1 + CC * CC,
                            Ws2 + CC * CC, Wsk + CC * CC, (const float*)0);

    k_out<<<1184, 256>>>(0, Wout, Wc, out);
}